// round 7
// baseline (speedup 1.0000x reference)
#include <cuda_runtime.h>
#include <cuda_bf16.h>
#include <float.h>
#include <math.h>

// Problem shape (fixed by reference setup_inputs)
#define B_   16
#define C_   256
#define H_   128
#define W_   128
#define HW_  (H_ * W_)           // 16384
#define HW4_ (HW_ / 4)           // 4096 float4 columns per image

// Scratch: feat [B, 2, H, W]  (avg then max)
__device__ float g_feat[B_ * 2 * HW_];

// ---------------------------------------------------------------------------
// Kernel 1: channel-wise mean + max over C=256.
// Block = quarter spatial row: 128 thr = (8 float4 cols) x (16 splits of 16 ch).
// 8192 blocks of 32 KB each: same 16 loads/thread and fan-in-16 reduce as R6,
// but half the work quantum -> finer tail + finer HW work-stealing.
// ---------------------------------------------------------------------------
__global__ __launch_bounds__(128) void reduce_mean_max_kernel(
    const float* __restrict__ x)
{
    cudaTriggerProgrammaticLaunchCompletion();

    __shared__ float4 s_sum[128];
    __shared__ float4 s_max[128];

    const int tid = threadIdx.x;
    const int col = tid & 7;                   // float4 column within quarter
    const int cs  = tid >> 3;                  // channel split 0..15

    const int blk  = blockIdx.x;               // 0..8191
    const int b    = blk >> 9;                 // 512 blocks per image
    const int q    = blk & 511;
    const int h    = q >> 2;                   // row
    const int quar = q & 3;                    // quarter within row
    const int hw4  = (h << 5) + (quar << 3) + col;

    const float4* xb = reinterpret_cast<const float4*>(x)
                     + (size_t)b * C_ * HW4_ + (size_t)(cs * 16) * HW4_ + hw4;

    float4 s = make_float4(0.f, 0.f, 0.f, 0.f);
    float4 m = make_float4(-FLT_MAX, -FLT_MAX, -FLT_MAX, -FLT_MAX);

    #pragma unroll
    for (int c = 0; c < 16; ++c) {
        float4 v = __ldcs(xb + (size_t)c * HW4_);
        s.x += v.x; s.y += v.y; s.z += v.z; s.w += v.w;
        m.x = fmaxf(m.x, v.x); m.y = fmaxf(m.y, v.y);
        m.z = fmaxf(m.z, v.z); m.w = fmaxf(m.w, v.w);
    }

    s_sum[tid] = s;
    s_max[tid] = m;
    __syncthreads();

    if (tid < 8) {
        #pragma unroll
        for (int k = 1; k < 16; ++k) {
            float4 ps = s_sum[tid + k * 8];
            float4 pm = s_max[tid + k * 8];
            s.x += ps.x; s.y += ps.y; s.z += ps.z; s.w += ps.w;
            m.x = fmaxf(m.x, pm.x); m.y = fmaxf(m.y, pm.y);
            m.z = fmaxf(m.z, pm.z); m.w = fmaxf(m.w, pm.w);
        }
        const float inv = 1.0f / (float)C_;
        float4 a = make_float4(s.x * inv, s.y * inv, s.z * inv, s.w * inv);

        float4* fa = reinterpret_cast<float4*>(g_feat)
                   + (size_t)b * 2 * HW4_ + hw4;
        fa[0]    = a;   // channel 0: avg
        fa[HW4_] = m;   // channel 1: max
    }
}

// ---------------------------------------------------------------------------
// Kernel 2: 3x3 conv (2 in ch, 1 out ch, pad 1, no bias) + sigmoid.
// One thread per output pixel (fastest measured config). PDL: weights load in
// the prologue, grid dependency sync, then conv against L2-hot g_feat.
// ---------------------------------------------------------------------------
__global__ __launch_bounds__(256) void conv_sigmoid_kernel(
    const float* __restrict__ conv_w,   // [1,2,3,3] OIHW
    float* __restrict__ out)            // [B,1,H,W]
{
    const int idx = blockIdx.x * blockDim.x + threadIdx.x;  // 0 .. B*HW-1
    const int b  = idx >> 14;           // / HW_
    const int hw = idx & (HW_ - 1);
    const int h  = hw >> 7;             // / W_
    const int w  = hw & (W_ - 1);

    // Prologue (overlaps producer drain): weights into registers.
    float wk[18];
    #pragma unroll
    for (int i = 0; i < 18; ++i) wk[i] = __ldg(conv_w + i);

    cudaGridDependencySynchronize();

    const float* f0 = g_feat + (size_t)b * 2 * HW_;   // avg channel
    const float* f1 = f0 + HW_;                       // max channel

    float acc = 0.f;
    #pragma unroll
    for (int kh = 0; kh < 3; ++kh) {
        const int hh = h + kh - 1;
        if (hh < 0 || hh >= H_) continue;
        #pragma unroll
        for (int kw = 0; kw < 3; ++kw) {
            const int ww = w + kw - 1;
            if (ww < 0 || ww >= W_) continue;
            const int off = hh * W_ + ww;
            acc = fmaf(f0[off], wk[kh * 3 + kw], acc);
            acc = fmaf(f1[off], wk[9 + kh * 3 + kw], acc);
        }
    }

    out[idx] = 1.0f / (1.0f + __expf(-acc));
}

// ---------------------------------------------------------------------------
extern "C" void kernel_launch(void* const* d_in, const int* in_sizes, int n_in,
                              void* d_out, int out_size)
{
    const float* x      = (const float*)d_in[0];   // [16,256,128,128] f32
    const float* conv_w = (const float*)d_in[1];   // [1,2,3,3] f32
    float*       out    = (float*)d_out;           // [16,1,128,128] f32

    // Kernel 1: 8192 blocks x 128 threads
    reduce_mean_max_kernel<<<8192, 128>>>(x);

    // Kernel 2: 1024 blocks x 256 threads, PDL-overlapped launch
    cudaLaunchConfig_t cfg = {};
    cfg.gridDim  = dim3((B_ * HW_) / 256, 1, 1);
    cfg.blockDim = dim3(256, 1, 1);
    cfg.dynamicSmemBytes = 0;
    cfg.stream = 0;

    cudaLaunchAttribute attrs[1];
    attrs[0].id = cudaLaunchAttributeProgrammaticStreamSerialization;
    attrs[0].val.programmaticStreamSerializationAllowed = 1;
    cfg.attrs = attrs;
    cfg.numAttrs = 1;

    cudaLaunchKernelEx(&cfg, conv_sigmoid_kernel, conv_w, out);
}

// round 8
// speedup vs baseline: 1.0384x; 1.0384x over previous
#include <cuda_runtime.h>
#include <cuda_bf16.h>
#include <float.h>
#include <math.h>

// Problem shape (fixed by reference setup_inputs)
#define B_   16
#define C_   256
#define H_   128
#define W_   128
#define HW_  (H_ * W_)           // 16384
#define HW4_ (HW_ / 4)           // 4096 float4 columns per image

// Scratch: feat [B, 2, H, W]  (avg then max)
__device__ float g_feat[B_ * 2 * HW_];

// ---------------------------------------------------------------------------
// Kernel 1: channel-wise mean + max over C=256.  (R6 config — best measured)
// Block = half a spatial row: (16 float4 cols) x (16 channel-splits of 16 ch).
// 4096 blocks x 256 threads.
// ---------------------------------------------------------------------------
__global__ __launch_bounds__(256) void reduce_mean_max_kernel(
    const float* __restrict__ x)
{
    cudaTriggerProgrammaticLaunchCompletion();

    __shared__ float4 s_sum[256];
    __shared__ float4 s_max[256];

    const int tid  = threadIdx.x;
    const int col  = tid & 15;                 // float4 column within half-row
    const int cs   = tid >> 4;                 // channel split 0..15

    const int blk    = blockIdx.x;             // 0..4095
    const int row_id = blk >> 1;               // 0..2047 == b*128 + h
    const int half   = blk & 1;
    const int b      = row_id >> 7;
    const int h      = row_id & 127;
    const int hw4    = (h << 5) + (half << 4) + col;

    const float4* xb = reinterpret_cast<const float4*>(x)
                     + (size_t)b * C_ * HW4_ + (size_t)(cs * 16) * HW4_ + hw4;

    float4 s = make_float4(0.f, 0.f, 0.f, 0.f);
    float4 m = make_float4(-FLT_MAX, -FLT_MAX, -FLT_MAX, -FLT_MAX);

    #pragma unroll
    for (int c = 0; c < 16; ++c) {
        float4 v = __ldcs(xb + (size_t)c * HW4_);
        s.x += v.x; s.y += v.y; s.z += v.z; s.w += v.w;
        m.x = fmaxf(m.x, v.x); m.y = fmaxf(m.y, v.y);
        m.z = fmaxf(m.z, v.z); m.w = fmaxf(m.w, v.w);
    }

    s_sum[tid] = s;
    s_max[tid] = m;
    __syncthreads();

    if (tid < 16) {
        #pragma unroll
        for (int k = 1; k < 16; ++k) {
            float4 ps = s_sum[tid + k * 16];
            float4 pm = s_max[tid + k * 16];
            s.x += ps.x; s.y += ps.y; s.z += ps.z; s.w += ps.w;
            m.x = fmaxf(m.x, pm.x); m.y = fmaxf(m.y, pm.y);
            m.z = fmaxf(m.z, pm.z); m.w = fmaxf(m.w, pm.w);
        }
        const float inv = 1.0f / (float)C_;
        float4 a = make_float4(s.x * inv, s.y * inv, s.z * inv, s.w * inv);

        float4* fa = reinterpret_cast<float4*>(g_feat)
                   + (size_t)b * 2 * HW4_ + hw4;
        fa[0]    = a;   // channel 0: avg
        fa[HW4_] = m;   // channel 1: max
    }
}

// ---------------------------------------------------------------------------
// Kernel 2: 3x3 conv (2 in ch, pad 1, no bias) + sigmoid, smem-tiled.
// Block = 4 output rows x 128 wide. Cooperative load of the 6-row x 2-ch halo
// (1536 floats, 6 per thread) into smem; each thread computes 2 pixels.
// L2 accesses per pixel: 3 (was 18).
// ---------------------------------------------------------------------------
#define TILE_H 4
__global__ __launch_bounds__(256) void conv_sigmoid_kernel(
    const float* __restrict__ conv_w,   // [1,2,3,3] OIHW
    float* __restrict__ out)            // [B,1,H,W]
{
    __shared__ float s_f[2][TILE_H + 2][W_];
    __shared__ float s_w[18];

    const int tid = threadIdx.x;

    // Prologue (overlaps producer drain): weights into smem.
    if (tid < 18) s_w[tid] = __ldg(conv_w + tid);

    cudaGridDependencySynchronize();

    const int blk = blockIdx.x;          // 0..511
    const int b   = blk >> 5;            // 32 tiles per image
    const int h0  = (blk & 31) * TILE_H;

    const float* fb = g_feat + (size_t)b * 2 * HW_;

    // Cooperative halo load: rows h0-1 .. h0+TILE_H, both channels.
    #pragma unroll
    for (int i = 0; i < 6; ++i) {
        const int idx = tid + i * 256;   // 0..1535
        const int ch  = idx / ((TILE_H + 2) * W_);          // 0..1
        const int rem = idx - ch * (TILE_H + 2) * W_;
        const int r   = rem >> 7;        // 0..5
        const int w   = rem & 127;
        const int hh  = h0 - 1 + r;
        float v = 0.f;
        if (hh >= 0 && hh < H_) v = fb[ch * HW_ + hh * W_ + w];
        s_f[ch][r][w] = v;
    }
    __syncthreads();

    // Each thread computes 2 pixels of the 4x128 tile.
    #pragma unroll
    for (int k = 0; k < 2; ++k) {
        const int p = tid + k * 256;     // 0..511
        const int r = p >> 7;            // local row 0..3
        const int w = p & 127;

        float acc = 0.f;
        #pragma unroll
        for (int kh = 0; kh < 3; ++kh) {
            #pragma unroll
            for (int kw = 0; kw < 3; ++kw) {
                const int ww = w + kw - 1;
                if (ww < 0 || ww >= W_) continue;
                acc = fmaf(s_f[0][r + kh][ww], s_w[kh * 3 + kw],     acc);
                acc = fmaf(s_f[1][r + kh][ww], s_w[9 + kh * 3 + kw], acc);
            }
        }
        out[(size_t)b * HW_ + (h0 + r) * W_ + w] = 1.0f / (1.0f + __expf(-acc));
    }
}

// ---------------------------------------------------------------------------
extern "C" void kernel_launch(void* const* d_in, const int* in_sizes, int n_in,
                              void* d_out, int out_size)
{
    const float* x      = (const float*)d_in[0];   // [16,256,128,128] f32
    const float* conv_w = (const float*)d_in[1];   // [1,2,3,3] f32
    float*       out    = (float*)d_out;           // [16,1,128,128] f32

    // Kernel 1: 4096 blocks x 256 threads (R6 best)
    reduce_mean_max_kernel<<<4096, 256>>>(x);

    // Kernel 2: 512 blocks x 256 threads, PDL-overlapped launch
    cudaLaunchConfig_t cfg = {};
    cfg.gridDim  = dim3(B_ * (H_ / TILE_H), 1, 1);   // 512
    cfg.blockDim = dim3(256, 1, 1);
    cfg.dynamicSmemBytes = 0;
    cfg.stream = 0;

    cudaLaunchAttribute attrs[1];
    attrs[0].id = cudaLaunchAttributeProgrammaticStreamSerialization;
    attrs[0].val.programmaticStreamSerializationAllowed = 1;
    cfg.attrs = attrs;
    cfg.numAttrs = 1;

    cudaLaunchKernelEx(&cfg, conv_sigmoid_kernel, conv_w, out);
}